// round 14
// baseline (speedup 1.0000x reference)
#include <cuda_runtime.h>
#include <cuda_fp16.h>
#include <math.h>
#include <stdint.h>

// Problem constants
#define NG   16          // NUM_GRIDS
#define NIX  32          // IN_X
#define NIZ  32          // IN_Z
#define NOUT 64          // OUT
#define NB   512         // BATCH
#define NC   17          // NUM_GRIDS + 1
#define IJ   (NIX * NIZ)         // 1024
#define JSTRH (IJ * NOUT)        // 65536 halfs: jj -> jj+1 step in P2h
#define ISTRH (NC * JSTRH)       // ii -> ii+1 step in P2h

// Repacked parameter tensor in fp16: P2h[cell][ij][o]  (o contiguous)
__device__ __half g_P2h[NC * NC * IJ * NOUT];

// ---------------------------------------------------------------------------
// Repack v4 (round-12 proven, ~16us = byte floor): tile 64 o x 64 ij,
// 4 back-to-back float4 LDGs (MLP=4), pitch-65 smem, uint4 half stores.
// ---------------------------------------------------------------------------
__global__ __launch_bounds__(256) void repack_kernel(const float* __restrict__ P) {
    __shared__ float tile[NOUT * 65];         // 16.6 KB
    const int cell = blockIdx.x >> 4;         // 0..288
    const int ij0  = (blockIdx.x & 15) << 6;  // 0..960
    const int t    = threadIdx.x;

    const float* src = P     + cell * (NOUT * IJ) + ij0;
    __half*      dst = g_P2h + cell * (IJ * NOUT) + ij0 * NOUT;

    float4 v4[4];
#pragma unroll
    for (int p = 0; p < 4; ++p) {
        const int f = t + p * 256;
        const int o = f >> 4;                 // 0..63
        const int c = f & 15;                 // 0..15
        v4[p] = *reinterpret_cast<const float4*>(src + o * IJ + c * 4);
    }
#pragma unroll
    for (int p = 0; p < 4; ++p) {
        const int f = t + p * 256;
        const int o = f >> 4;
        const int c = f & 15;
        float* tp = tile + o * 65 + c * 4;
        tp[0] = v4[p].x; tp[1] = v4[p].y; tp[2] = v4[p].z; tp[3] = v4[p].w;
    }
    __syncthreads();

#pragma unroll
    for (int p = 0; p < 2; ++p) {
        const int item = t + p * 256;
        const int ij = item >> 3;             // 0..63
        const int og = item & 7;              // 0..7
        float v[8];
#pragma unroll
        for (int m = 0; m < 8; ++m)
            v[m] = tile[(og * 8 + m) * 65 + ij];
        __half2 h0 = __floats2half2_rn(v[0], v[1]);
        __half2 h1 = __floats2half2_rn(v[2], v[3]);
        __half2 h2 = __floats2half2_rn(v[4], v[5]);
        __half2 h3 = __floats2half2_rn(v[6], v[7]);
        uint4 q;
        q.x = *reinterpret_cast<unsigned*>(&h0);
        q.y = *reinterpret_cast<unsigned*>(&h1);
        q.z = *reinterpret_cast<unsigned*>(&h2);
        q.w = *reinterpret_cast<unsigned*>(&h3);
        *reinterpret_cast<uint4*>(dst + ij * NOUT + og * 8) = q;
    }
}

// ---------------------------------------------------------------------------
// fp16x8 weighted accumulate: acc[0..7] += w * (8 halfs in q).
// 8 independent f32 FFMA chains -- the latency-hiding resource (rounds 6/9:
// replacing with fp16 chains regresses; do not touch).
// ---------------------------------------------------------------------------
__device__ __forceinline__ void accum8(float acc[8], uint4 q, float w) {
    const __half2* h = reinterpret_cast<const __half2*>(&q);
#pragma unroll
    for (int m = 0; m < 4; ++m) {
        const float2 f = __half22float2(h[m]);
        acc[2 * m + 0] += w * f.x;
        acc[2 * m + 1] += w * f.y;
    }
}

// ---------------------------------------------------------------------------
// Gather v6: round-12 proven structure + smem-hoisted per-cell base/weights
// (the one combination never tested: hoisting WITH the f32 accum8 loop).
// Inner loop per cell: 1 LDS + 1 LDS.128 + 4 LDG.128 + accum8 x4
// (~54 instr vs ~62 inline). grid (NB), block 512, same ij sweep order
// across all blocks (cross-batch L1/L2 reuse -- proven).
// ---------------------------------------------------------------------------
__global__ __launch_bounds__(512) void gather_kernel(
    const float* __restrict__ x,
    const float* __restrict__ z,
    const float* __restrict__ borders,
    const float* __restrict__ invlen,
    float* __restrict__ out)
{
    const int b   = blockIdx.x;
    const int tid = threadIdx.x;

    __shared__ float  s_dx[NIX];
    __shared__ float  s_dz[NIZ];
    __shared__ int    s_ixw[NIX];    // bin_x * NC
    __shared__ int    s_izb[NIZ];    // bin_z
    __shared__ int    s_base[IJ];    // 4 KB: cell base (half units)
    __shared__ float4 s_wf[IJ];      // 16 KB: f32 bilinear weights

    // Pass 0: per-row/col bin + fractional offset (laplace cdf binning)
    if (tid < 64) {
        const float v = (tid < 32) ? x[tid * NB + b] : z[(tid - 32) * NB + b];
        const float e = __expf(-fabsf(v));
        const float cdf = (v > 0.0f) ? (1.0f - 0.5f * e) : (0.5f * e);
        int idx = (int)(cdf * (float)NG);
        idx = max(0, min(NG - 1, idx));
        const float d = (v - borders[idx]) * invlen[idx];
        if (tid < 32) { s_ixw[tid] = idx * NC;    s_dx[tid] = d; }
        else          { s_izb[tid - 32] = idx;    s_dz[tid - 32] = d; }
    }
    __syncthreads();

    // Pass 1: per-cell base + f32 weights (2 cells per thread)
#pragma unroll
    for (int c = 0; c < IJ / 512; ++c) {
        const int ij = tid + c * 512;
        const int i = ij >> 5;
        const int j = ij & 31;
        const float dx = s_dx[i];
        const float dz = s_dz[j];
        const float ax = 1.0f - dx;
        const float az = 1.0f - dz;
        s_wf[ij]   = make_float4(ax * az, ax * dz, dx * az, dx * dz);
        s_base[ij] = ((s_ixw[i] + s_izb[j]) * IJ + ij) * NOUT;
    }
    __syncthreads();

    const int og  = tid & 7;        // o-group: halfs [og*8, og*8+8) of 64
    const int ijg = tid >> 3;       // ij-group 0..63
    const int ooff = og * 8;

    float acc[8];
#pragma unroll
    for (int e = 0; e < 8; ++e) acc[e] = 0.0f;

#pragma unroll 8
    for (int k = 0; k < IJ / 64; ++k) {     // 16 sweep steps
        const int ij = ijg + (k << 6);
        const int base = s_base[ij] + ooff;  // LDS, 4 addrs/warp
        const float4 w = s_wf[ij];           // LDS.128, 4 addrs/warp
        const __half* p = g_P2h + base;

        const uint4 q00 = *reinterpret_cast<const uint4*>(p);
        const uint4 q01 = *reinterpret_cast<const uint4*>(p + JSTRH);
        const uint4 q10 = *reinterpret_cast<const uint4*>(p + ISTRH);
        const uint4 q11 = *reinterpret_cast<const uint4*>(p + ISTRH + JSTRH);

        accum8(acc, q00, w.x);
        accum8(acc, q01, w.y);
        accum8(acc, q10, w.z);
        accum8(acc, q11, w.w);
    }

    // Warp reduction over the 4 ij-groups per warp (lane = (ijg&3)*8 + og)
#pragma unroll
    for (int m = 8; m <= 16; m <<= 1)
#pragma unroll
        for (int e = 0; e < 8; ++e)
            acc[e] += __shfl_xor_sync(0xffffffffu, acc[e], m);

    // Cross-warp reduction: 16 warps x 8 o-groups x 8 elems
    __shared__ float s_part[16][8][8];
    const int warp = tid >> 5;
    const int lane = tid & 31;
    if (lane < 8) {
#pragma unroll
        for (int e = 0; e < 8; ++e) s_part[warp][lane][e] = acc[e];
    }
    __syncthreads();

    if (tid < 64) {
        const int og2 = tid >> 3;       // o-group
        const int e   = tid & 7;        // element within group
        float a = s_part[0][og2][e];
#pragma unroll
        for (int w = 1; w < 16; ++w) a += s_part[w][og2][e];
        out[(og2 * 8 + e) * NB + b] = a;
    }
}

// ---------------------------------------------------------------------------
extern "C" void kernel_launch(void* const* d_in, const int* in_sizes, int n_in,
                              void* d_out, int out_size) {
    const float* x       = (const float*)d_in[0];  // (32, 512)
    const float* z       = (const float*)d_in[1];  // (32, 512)
    const float* P       = (const float*)d_in[2];  // (17,17,64,32,32)
    const float* borders = (const float*)d_in[3];  // (17,)
    const float* invlen  = (const float*)d_in[4];  // (16,)
    float* out = (float*)d_out;                    // (64, 512)

    (void)in_sizes; (void)n_in; (void)out_size;

    // Phase 1: repack P -> P2h (fp16, o contiguous), MLP=4 loads
    {
        repack_kernel<<<NC * NC * 16, 256>>>(P);   // 4624 blocks
    }

    // Phase 2: gather + accumulate (hoisted meta + f32 accum8)
    {
        gather_kernel<<<NB, 512>>>(x, z, borders, invlen, out);
    }
}